// round 2
// baseline (speedup 1.0000x reference)
#include <cuda_runtime.h>
#include <math.h>

#define Bb 16
#define Tt 1024
#define Ss 2048
#define Hh 1024

// Scratch (allocation-free rule: __device__ globals)
__device__ float g_q[(long)Bb * Tt * Hh];    // 64 MB
__device__ float g_mix[(long)Bb * Tt * Hh];  // 64 MB

// ---------------------------------------------------------------------------
// Generic tiled SGEMM: C[M,N] = A[M,K] * op(B)
//   BT=true : B is row-major [N,K]  (C[m,n] = sum_k A[m,k]*B[n,k])   "NT"
//   BT=false: B is row-major [K,N]  (C[m,n] = sum_k A[m,k]*B[k,n])   "NN"
// Tile: 128x128x16, 256 threads, 8x8 per thread. All dims assumed multiples
// of tile sizes (true for this problem).
// ---------------------------------------------------------------------------
template <bool BT>
__global__ __launch_bounds__(256, 2)
void sgemm_kernel(const float* __restrict__ A, const float* __restrict__ Bm,
                  float* __restrict__ C,
                  int M, int N, int K, int lda, int ldb, int ldc,
                  long strideA, long strideB, long strideC)
{
    __shared__ float As[16][128];
    __shared__ float Bs[16][128];

    const int bz = blockIdx.z;
    A  += (long)bz * strideA;
    Bm += (long)bz * strideB;
    C  += (long)bz * strideC;

    const int m0 = blockIdx.y * 128;
    const int n0 = blockIdx.x * 128;
    const int tid = threadIdx.x;
    const int tx = tid & 15;   // 0..15 -> N direction (8 cols each)
    const int ty = tid >> 4;   // 0..15 -> M direction (8 rows each)

    float acc[8][8];
#pragma unroll
    for (int i = 0; i < 8; i++)
#pragma unroll
        for (int j = 0; j < 8; j++) acc[i][j] = 0.f;

    for (int k0 = 0; k0 < K; k0 += 16) {
        // --- load A tile (row-major MxK): As[k][m] ---
#pragma unroll
        for (int l = 0; l < 2; l++) {
            int v   = tid + l * 256;       // 0..511 float4 slots
            int row = v >> 2;              // 0..127
            int kv  = (v & 3) * 4;         // 0,4,8,12
            float4 t = *(const float4*)&A[(long)(m0 + row) * lda + k0 + kv];
            As[kv + 0][row] = t.x;
            As[kv + 1][row] = t.y;
            As[kv + 2][row] = t.z;
            As[kv + 3][row] = t.w;
        }
        // --- load B tile ---
        if (BT) {
#pragma unroll
            for (int l = 0; l < 2; l++) {
                int v   = tid + l * 256;
                int row = v >> 2;
                int kv  = (v & 3) * 4;
                float4 t = *(const float4*)&Bm[(long)(n0 + row) * ldb + k0 + kv];
                Bs[kv + 0][row] = t.x;
                Bs[kv + 1][row] = t.y;
                Bs[kv + 2][row] = t.z;
                Bs[kv + 3][row] = t.w;
            }
        } else {
#pragma unroll
            for (int l = 0; l < 2; l++) {
                int v  = tid + l * 256;
                int kk = v >> 5;            // 0..15
                int nv = (v & 31) * 4;      // 0..124
                *(float4*)&Bs[kk][nv] =
                    *(const float4*)&Bm[(long)(k0 + kk) * ldb + n0 + nv];
            }
        }
        __syncthreads();

#pragma unroll
        for (int kk = 0; kk < 16; kk++) {
            float a[8], b[8];
            *(float4*)&a[0] = *(float4*)&As[kk][ty * 8];
            *(float4*)&a[4] = *(float4*)&As[kk][ty * 8 + 4];
            *(float4*)&b[0] = *(float4*)&Bs[kk][tx * 8];
            *(float4*)&b[4] = *(float4*)&Bs[kk][tx * 8 + 4];
#pragma unroll
            for (int i = 0; i < 8; i++)
#pragma unroll
                for (int j = 0; j < 8; j++)
                    acc[i][j] += a[i] * b[j];
        }
        __syncthreads();
    }

#pragma unroll
    for (int i = 0; i < 8; i++) {
#pragma unroll
        for (int j = 0; j < 8; j += 4) {
            float4 t = make_float4(acc[i][j], acc[i][j + 1], acc[i][j + 2], acc[i][j + 3]);
            *(float4*)&C[(long)(m0 + ty * 8 + i) * ldc + n0 + tx * 8 + j] = t;
        }
    }
}

// ---------------------------------------------------------------------------
// Final GEMM: out[m,n] = tanh( sum_{k<2048} comb[m,k]*W2[n,k] + bias[n] )
// comb[m,k] = (k < 1024) ? mix[m,k] : q[m,k-1024].  W2 row-major [1024,2048].
// ---------------------------------------------------------------------------
__global__ __launch_bounds__(256, 2)
void out_gemm_kernel(const float* __restrict__ mix, const float* __restrict__ q,
                     const float* __restrict__ W2, const float* __restrict__ bias,
                     float* __restrict__ out)
{
    __shared__ float As[16][128];
    __shared__ float Bs[16][128];

    const int m0 = blockIdx.y * 128;
    const int n0 = blockIdx.x * 128;
    const int tid = threadIdx.x;
    const int tx = tid & 15;
    const int ty = tid >> 4;

    float acc[8][8];
#pragma unroll
    for (int i = 0; i < 8; i++)
#pragma unroll
        for (int j = 0; j < 8; j++) acc[i][j] = 0.f;

    for (int k0 = 0; k0 < 2 * Hh; k0 += 16) {
        const float* Asrc = (k0 < Hh) ? mix : q;
        const int kofs = k0 & (Hh - 1);
#pragma unroll
        for (int l = 0; l < 2; l++) {
            int v   = tid + l * 256;
            int row = v >> 2;
            int kv  = (v & 3) * 4;
            float4 t = *(const float4*)&Asrc[(long)(m0 + row) * Hh + kofs + kv];
            As[kv + 0][row] = t.x;
            As[kv + 1][row] = t.y;
            As[kv + 2][row] = t.z;
            As[kv + 3][row] = t.w;
        }
#pragma unroll
        for (int l = 0; l < 2; l++) {
            int v   = tid + l * 256;
            int row = v >> 2;
            int kv  = (v & 3) * 4;
            float4 t = *(const float4*)&W2[(long)(n0 + row) * (2 * Hh) + k0 + kv];
            Bs[kv + 0][row] = t.x;
            Bs[kv + 1][row] = t.y;
            Bs[kv + 2][row] = t.z;
            Bs[kv + 3][row] = t.w;
        }
        __syncthreads();

#pragma unroll
        for (int kk = 0; kk < 16; kk++) {
            float a[8], b[8];
            *(float4*)&a[0] = *(float4*)&As[kk][ty * 8];
            *(float4*)&a[4] = *(float4*)&As[kk][ty * 8 + 4];
            *(float4*)&b[0] = *(float4*)&Bs[kk][tx * 8];
            *(float4*)&b[4] = *(float4*)&Bs[kk][tx * 8 + 4];
#pragma unroll
            for (int i = 0; i < 8; i++)
#pragma unroll
                for (int j = 0; j < 8; j++)
                    acc[i][j] += a[i] * b[j];
        }
        __syncthreads();
    }

#pragma unroll
    for (int i = 0; i < 8; i++) {
#pragma unroll
        for (int j = 0; j < 8; j += 4) {
            int n = n0 + tx * 8 + j;
            float4 t;
            t.x = tanhf(acc[i][j + 0] + bias[n + 0]);
            t.y = tanhf(acc[i][j + 1] + bias[n + 1]);
            t.z = tanhf(acc[i][j + 2] + bias[n + 2]);
            t.w = tanhf(acc[i][j + 3] + bias[n + 3]);
            *(float4*)&out[(long)(m0 + ty * 8 + i) * Hh + n] = t;
        }
    }
}

// ---------------------------------------------------------------------------
// In-place row softmax over S=2048 (one block per row, 256 threads x 8 elems)
// ---------------------------------------------------------------------------
__global__ __launch_bounds__(256)
void softmax_kernel(float* __restrict__ attn)
{
    __shared__ float red[256];
    const long row = blockIdx.x;
    float* p = attn + row * (long)Ss;
    const int tid = threadIdx.x;

    float v[8];
    float mx = -INFINITY;
#pragma unroll
    for (int i = 0; i < 8; i++) {
        v[i] = p[tid + i * 256];
        mx = fmaxf(mx, v[i]);
    }
    red[tid] = mx;
    __syncthreads();
    for (int s = 128; s > 0; s >>= 1) {
        if (tid < s) red[tid] = fmaxf(red[tid], red[tid + s]);
        __syncthreads();
    }
    mx = red[0];
    __syncthreads();

    float sum = 0.f;
#pragma unroll
    for (int i = 0; i < 8; i++) {
        v[i] = __expf(v[i] - mx);
        sum += v[i];
    }
    red[tid] = sum;
    __syncthreads();
    for (int s = 128; s > 0; s >>= 1) {
        if (tid < s) red[tid] += red[tid + s];
        __syncthreads();
    }
    const float inv = 1.f / red[0];
#pragma unroll
    for (int i = 0; i < 8; i++)
        p[tid + i * 256] = v[i] * inv;
}

// ---------------------------------------------------------------------------
extern "C" void kernel_launch(void* const* d_in, const int* in_sizes, int n_in,
                              void* d_out, int out_size)
{
    const float* output  = (const float*)d_in[0];  // [B,T,H]
    const float* context = (const float*)d_in[1];  // [B,S,H]
    const float* attn_w  = (const float*)d_in[2];  // [H,H]
    const float* w2      = (const float*)d_in[3];  // [H,2H]
    const float* b2      = (const float*)d_in[4];  // [H]

    float* out  = (float*)d_out;                       // [B,T,H]
    float* attn = out + (long)Bb * Tt * Hh;            // [B,T,S]

    float* qp   = nullptr;
    float* mixp = nullptr;
    cudaGetSymbolAddress((void**)&qp, g_q);
    cudaGetSymbolAddress((void**)&mixp, g_mix);

    // 1) q = output @ attn_w^T   (NT, M=B*T=16384, N=H, K=H)
    {
        dim3 grid(Hh / 128, (Bb * Tt) / 128, 1);
        sgemm_kernel<true><<<grid, 256>>>(output, attn_w, qp,
                                          Bb * Tt, Hh, Hh, Hh, Hh, Hh,
                                          0L, 0L, 0L);
    }
    // 2) scores = q @ context^T  per batch (NT, M=T, N=S, K=H) -> attn region
    {
        dim3 grid(Ss / 128, Tt / 128, Bb);
        sgemm_kernel<true><<<grid, 256>>>(qp, context, attn,
                                          Tt, Ss, Hh, Hh, Hh, Ss,
                                          (long)Tt * Hh, (long)Ss * Hh, (long)Tt * Ss);
    }
    // 3) softmax rows in place
    softmax_kernel<<<Bb * Tt, 256>>>(attn);

    // 4) mix = attn @ context    per batch (NN, M=T, N=H, K=S)
    {
        dim3 grid(Hh / 128, Tt / 128, Bb);
        sgemm_kernel<false><<<grid, 256>>>(attn, context, mixp,
                                           Tt, Hh, Ss, Ss, Hh, Hh,
                                           (long)Tt * Ss, (long)Ss * Hh, (long)Tt * Hh);
    }
    // 5) out = tanh([mix, q] @ w2^T + b2)
    {
        dim3 grid(Hh / 128, (Bb * Tt) / 128, 1);
        out_gemm_kernel<<<grid, 256>>>(mixp, qp, w2, b2, out);
    }
}

// round 6
// speedup vs baseline: 1.0283x; 1.0283x over previous
#include <cuda_runtime.h>
#include <math.h>

#define Bb 16
#define Tt 1024
#define Ss 2048
#define Hh 1024

// Scratch (allocation-free rule: __device__ globals)
__device__ float g_q[(long)Bb * Tt * Hh];    // 64 MB
__device__ float g_mix[(long)Bb * Tt * Hh];  // 64 MB

// Packed f32x2 FMA: d.lo += a.lo*b.lo ; d.hi += a.hi*b.hi  (one issue, 2 FMAs)
#define FMA_F32X2(acc, a, b) \
    asm("fma.rn.f32x2 %0, %1, %2, %0;" : "+l"(acc) : "l"(a), "l"(b))
#define DUP_F32X2(d, s) \
    asm("mov.b64 %0, {%1, %1};" : "=l"(d) : "f"(s))

// ---------------------------------------------------------------------------
// Generic tiled SGEMM: C[M,N] = A[M,K] * op(B), f32x2-packed inner product.
//   BT=true : B row-major [N,K]  (NT)     BT=false: B row-major [K,N] (NN)
// Tile: 128x128x16, 256 threads, 8x8 per thread (4x f32x2 in N).
// ---------------------------------------------------------------------------
template <bool BT>
__global__ __launch_bounds__(256, 2)
void sgemm_kernel(const float* __restrict__ A, const float* __restrict__ Bm,
                  float* __restrict__ C,
                  int M, int N, int K, int lda, int ldb, int ldc,
                  long strideA, long strideB, long strideC)
{
    __shared__ float As[16][128];
    __shared__ float Bs[16][128];

    const int bz = blockIdx.z;
    A  += (long)bz * strideA;
    Bm += (long)bz * strideB;
    C  += (long)bz * strideC;

    const int m0 = blockIdx.y * 128;
    const int n0 = blockIdx.x * 128;
    const int tid = threadIdx.x;
    const int tx = tid & 15;   // N direction (8 cols each)
    const int ty = tid >> 4;   // M direction (8 rows each)

    unsigned long long acc2[8][4];
#pragma unroll
    for (int i = 0; i < 8; i++)
#pragma unroll
        for (int j = 0; j < 4; j++) acc2[i][j] = 0ULL;

    for (int k0 = 0; k0 < K; k0 += 16) {
        // --- load A tile (row-major MxK): As[k][m] ---
#pragma unroll
        for (int l = 0; l < 2; l++) {
            int v   = tid + l * 256;
            int row = v >> 2;
            int kv  = (v & 3) * 4;
            float4 t = *(const float4*)&A[(long)(m0 + row) * lda + k0 + kv];
            As[kv + 0][row] = t.x;
            As[kv + 1][row] = t.y;
            As[kv + 2][row] = t.z;
            As[kv + 3][row] = t.w;
        }
        // --- load B tile ---
        if (BT) {
#pragma unroll
            for (int l = 0; l < 2; l++) {
                int v   = tid + l * 256;
                int row = v >> 2;
                int kv  = (v & 3) * 4;
                float4 t = *(const float4*)&Bm[(long)(n0 + row) * ldb + k0 + kv];
                Bs[kv + 0][row] = t.x;
                Bs[kv + 1][row] = t.y;
                Bs[kv + 2][row] = t.z;
                Bs[kv + 3][row] = t.w;
            }
        } else {
#pragma unroll
            for (int l = 0; l < 2; l++) {
                int v  = tid + l * 256;
                int kk = v >> 5;
                int nv = (v & 31) * 4;
                *(float4*)&Bs[kk][nv] =
                    *(const float4*)&Bm[(long)(k0 + kk) * ldb + n0 + nv];
            }
        }
        __syncthreads();

#pragma unroll
        for (int kk = 0; kk < 16; kk++) {
            float a[8];
            *(float4*)&a[0] = *(float4*)&As[kk][ty * 8];
            *(float4*)&a[4] = *(float4*)&As[kk][ty * 8 + 4];
            unsigned long long bq[4];
            *(ulonglong2*)&bq[0] = *(ulonglong2*)&Bs[kk][tx * 8];
            *(ulonglong2*)&bq[2] = *(ulonglong2*)&Bs[kk][tx * 8 + 4];
#pragma unroll
            for (int i = 0; i < 8; i++) {
                unsigned long long ap;
                DUP_F32X2(ap, a[i]);
#pragma unroll
                for (int jj = 0; jj < 4; jj++)
                    FMA_F32X2(acc2[i][jj], ap, bq[jj]);
            }
        }
        __syncthreads();
    }

#pragma unroll
    for (int i = 0; i < 8; i++) {
        float4 t0, t1;
        t0.x = ((float2*)&acc2[i][0])->x;  t0.y = ((float2*)&acc2[i][0])->y;
        t0.z = ((float2*)&acc2[i][1])->x;  t0.w = ((float2*)&acc2[i][1])->y;
        t1.x = ((float2*)&acc2[i][2])->x;  t1.y = ((float2*)&acc2[i][2])->y;
        t1.z = ((float2*)&acc2[i][3])->x;  t1.w = ((float2*)&acc2[i][3])->y;
        float* cr = &C[(long)(m0 + ty * 8 + i) * ldc + n0 + tx * 8];
        *(float4*)&cr[0] = t0;
        *(float4*)&cr[4] = t1;
    }
}

// ---------------------------------------------------------------------------
// Final GEMM: out[m,n] = tanh( sum_{k<2048} comb[m,k]*W2[n,k] + bias[n] )
// comb[m,k] = (k < 1024) ? mix[m,k] : q[m,k-1024].  W2 row-major [1024,2048].
// ---------------------------------------------------------------------------
__global__ __launch_bounds__(256, 2)
void out_gemm_kernel(const float* __restrict__ mix, const float* __restrict__ q,
                     const float* __restrict__ W2, const float* __restrict__ bias,
                     float* __restrict__ out)
{
    __shared__ float As[16][128];
    __shared__ float Bs[16][128];

    const int m0 = blockIdx.y * 128;
    const int n0 = blockIdx.x * 128;
    const int tid = threadIdx.x;
    const int tx = tid & 15;
    const int ty = tid >> 4;

    unsigned long long acc2[8][4];
#pragma unroll
    for (int i = 0; i < 8; i++)
#pragma unroll
        for (int j = 0; j < 4; j++) acc2[i][j] = 0ULL;

    for (int k0 = 0; k0 < 2 * Hh; k0 += 16) {
        const float* Asrc = (k0 < Hh) ? mix : q;
        const int kofs = k0 & (Hh - 1);
#pragma unroll
        for (int l = 0; l < 2; l++) {
            int v   = tid + l * 256;
            int row = v >> 2;
            int kv  = (v & 3) * 4;
            float4 t = *(const float4*)&Asrc[(long)(m0 + row) * Hh + kofs + kv];
            As[kv + 0][row] = t.x;
            As[kv + 1][row] = t.y;
            As[kv + 2][row] = t.z;
            As[kv + 3][row] = t.w;
        }
#pragma unroll
        for (int l = 0; l < 2; l++) {
            int v   = tid + l * 256;
            int row = v >> 2;
            int kv  = (v & 3) * 4;
            float4 t = *(const float4*)&W2[(long)(n0 + row) * (2 * Hh) + k0 + kv];
            Bs[kv + 0][row] = t.x;
            Bs[kv + 1][row] = t.y;
            Bs[kv + 2][row] = t.z;
            Bs[kv + 3][row] = t.w;
        }
        __syncthreads();

#pragma unroll
        for (int kk = 0; kk < 16; kk++) {
            float a[8];
            *(float4*)&a[0] = *(float4*)&As[kk][ty * 8];
            *(float4*)&a[4] = *(float4*)&As[kk][ty * 8 + 4];
            unsigned long long bq[4];
            *(ulonglong2*)&bq[0] = *(ulonglong2*)&Bs[kk][tx * 8];
            *(ulonglong2*)&bq[2] = *(ulonglong2*)&Bs[kk][tx * 8 + 4];
#pragma unroll
            for (int i = 0; i < 8; i++) {
                unsigned long long ap;
                DUP_F32X2(ap, a[i]);
#pragma unroll
                for (int jj = 0; jj < 4; jj++)
                    FMA_F32X2(acc2[i][jj], ap, bq[jj]);
            }
        }
        __syncthreads();
    }

#pragma unroll
    for (int i = 0; i < 8; i++) {
        const int n = n0 + tx * 8;
        float v[8];
#pragma unroll
        for (int jj = 0; jj < 4; jj++) {
            float2 f = *(float2*)&acc2[i][jj];
            v[2 * jj + 0] = f.x;
            v[2 * jj + 1] = f.y;
        }
        float4 t0, t1;
        t0.x = tanhf(v[0] + bias[n + 0]);
        t0.y = tanhf(v[1] + bias[n + 1]);
        t0.z = tanhf(v[2] + bias[n + 2]);
        t0.w = tanhf(v[3] + bias[n + 3]);
        t1.x = tanhf(v[4] + bias[n + 4]);
        t1.y = tanhf(v[5] + bias[n + 5]);
        t1.z = tanhf(v[6] + bias[n + 6]);
        t1.w = tanhf(v[7] + bias[n + 7]);
        float* orow = &out[(long)(m0 + ty * 8 + i) * Hh + n];
        *(float4*)&orow[0] = t0;
        *(float4*)&orow[4] = t1;
    }
}

// ---------------------------------------------------------------------------
// In-place row softmax over S=2048 (one block per row, 256 threads x 8 elems)
// ---------------------------------------------------------------------------
__global__ __launch_bounds__(256)
void softmax_kernel(float* __restrict__ attn)
{
    __shared__ float red[256];
    const long row = blockIdx.x;
    float* p = attn + row * (long)Ss;
    const int tid = threadIdx.x;

    float v[8];
    float mx = -INFINITY;
#pragma unroll
    for (int i = 0; i < 8; i++) {
        v[i] = p[tid + i * 256];
        mx = fmaxf(mx, v[i]);
    }
    red[tid] = mx;
    __syncthreads();
    for (int s = 128; s > 0; s >>= 1) {
        if (tid < s) red[tid] = fmaxf(red[tid], red[tid + s]);
        __syncthreads();
    }
    mx = red[0];
    __syncthreads();

    float sum = 0.f;
#pragma unroll
    for (int i = 0; i < 8; i++) {
        v[i] = __expf(v[i] - mx);
        sum += v[i];
    }
    red[tid] = sum;
    __syncthreads();
    for (int s = 128; s > 0; s >>= 1) {
        if (tid < s) red[tid] += red[tid + s];
        __syncthreads();
    }
    const float inv = 1.f / red[0];
#pragma unroll
    for (int i = 0; i < 8; i++)
        p[tid + i * 256] = v[i] * inv;
}

// ---------------------------------------------------------------------------
extern "C" void kernel_launch(void* const* d_in, const int* in_sizes, int n_in,
                              void* d_out, int out_size)
{
    const float* output  = (const float*)d_in[0];  // [B,T,H]
    const float* context = (const float*)d_in[1];  // [B,S,H]
    const float* attn_w  = (const float*)d_in[2];  // [H,H]
    const float* w2      = (const float*)d_in[3];  // [H,2H]
    const float* b2      = (const float*)d_in[4];  // [H]

    float* out  = (float*)d_out;                   // [B,T,H]
    float* attn = out + (long)Bb * Tt * Hh;        // [B,T,S]

    float* qp   = nullptr;
    float* mixp = nullptr;
    cudaGetSymbolAddress((void**)&qp, g_q);
    cudaGetSymbolAddress((void**)&mixp, g_mix);

    // 1) q = output @ attn_w^T   (NT, M=B*T, N=H, K=H)
    {
        dim3 grid(Hh / 128, (Bb * Tt) / 128, 1);
        sgemm_kernel<true><<<grid, 256>>>(output, attn_w, qp,
                                          Bb * Tt, Hh, Hh, Hh, Hh, Hh,
                                          0L, 0L, 0L);
    }
    // 2) scores = q @ context^T  per batch (NT, M=T, N=S, K=H) -> attn region
    {
        dim3 grid(Ss / 128, Tt / 128, Bb);
        sgemm_kernel<true><<<grid, 256>>>(qp, context, attn,
                                          Tt, Ss, Hh, Hh, Hh, Ss,
                                          (long)Tt * Hh, (long)Ss * Hh, (long)Tt * Ss);
    }
    // 3) softmax rows in place
    softmax_kernel<<<Bb * Tt, 256>>>(attn);

    // 4) mix = attn @ context    per batch (NN, M=T, N=H, K=S)
    {
        dim3 grid(Hh / 128, Tt / 128, Bb);
        sgemm_kernel<false><<<grid, 256>>>(attn, context, mixp,
                                           Tt, Hh, Ss, Ss, Hh, Hh,
                                           (long)Tt * Ss, (long)Ss * Hh, (long)Tt * Hh);
    }
    // 5) out = tanh([mix, q] @ w2^T + b2)
    {
        dim3 grid(Hh / 128, (Bb * Tt) / 128, 1);
        out_gemm_kernel<<<grid, 256>>>(mixp, qp, w2, b2, out);
    }
}

// round 8
// speedup vs baseline: 2.2019x; 2.1414x over previous
#include <cuda_runtime.h>
#include <cuda_bf16.h>
#include <math.h>
#include <stdint.h>

#define Bb 16
#define Tt 1024
#define Ss 2048
#define Hh 1024
#define MT 16384          // B*T

// ---------------- global scratch (allocation-free rule) ---------------------
__device__ __nv_bfloat16 g_out_hi[(long)MT * Hh],  g_out_lo[(long)MT * Hh];
__device__ __nv_bfloat16 g_w_hi[(long)Hh * Hh],    g_w_lo[(long)Hh * Hh];
__device__ __nv_bfloat16 g_w2_hi[(long)Hh * 2 * Hh], g_w2_lo[(long)Hh * 2 * Hh];
__device__ __nv_bfloat16 g_ctx_hi[(long)Bb * Ss * Hh], g_ctx_lo[(long)Bb * Ss * Hh];
__device__ __nv_bfloat16 g_ctxT_hi[(long)Bb * Hh * Ss], g_ctxT_lo[(long)Bb * Hh * Ss];
__device__ __nv_bfloat16 g_q_hi[(long)MT * Hh],    g_q_lo[(long)MT * Hh];
__device__ __nv_bfloat16 g_attn_hi[(long)MT * Ss], g_attn_lo[(long)MT * Ss];
__device__ __nv_bfloat16 g_mix_hi[(long)MT * Hh],  g_mix_lo[(long)MT * Hh];

// ---------------- PTX helpers (all sm_80+ arch-agnostic) --------------------
__device__ __forceinline__ uint32_t smem_u32(const void* p) {
    uint32_t a;
    asm("{ .reg .u64 t; cvta.to.shared.u64 t, %1; cvt.u32.u64 %0, t; }" : "=r"(a) : "l"(p));
    return a;
}
#define CP_ASYNC16(dst, src) \
    asm volatile("cp.async.cg.shared.global [%0], [%1], 16;" :: "r"(dst), "l"(src) : "memory")
#define CP_COMMIT() asm volatile("cp.async.commit_group;" ::: "memory")
#define CP_WAIT2()  asm volatile("cp.async.wait_group 2;" ::: "memory")

#define LDM4(r, a) \
    asm volatile("ldmatrix.sync.aligned.m8n8.x4.shared.b16 {%0,%1,%2,%3}, [%4];" \
        : "=r"((r)[0]), "=r"((r)[1]), "=r"((r)[2]), "=r"((r)[3]) : "r"(a))

#define MMA_BF16(d, a, b0, b1) \
    asm volatile("mma.sync.aligned.m16n8k16.row.col.f32.bf16.bf16.f32 " \
        "{%0,%1,%2,%3}, {%4,%5,%6,%7}, {%8,%9}, {%0,%1,%2,%3};" \
        : "+f"((d)[0]), "+f"((d)[1]), "+f"((d)[2]), "+f"((d)[3]) \
        : "r"((a)[0]), "r"((a)[1]), "r"((a)[2]), "r"((a)[3]), "r"(b0), "r"(b1))

// SMEM layout per stage: Ahi[128][40] | Alo | Bhi[128][40] | Blo  (halves)
#define ROWB   80          // bytes per smem row (40 halves: 32 data + 8 pad)
#define MATB   10240       // bytes per matrix per stage
#define STG    40960       // bytes per stage
#define NSTG   3
#define SMEM_TOTAL (NSTG * STG)
#define KC     32

// ---------------------------------------------------------------------------
// HMMA bf16 GEMM with 2-term hi/lo split: C[M,N] = A[M,K] * B[N,K]^T
// CTA tile 128x128, 8 warps (4m x 2n), warp tile 32x64, K chunks of 32.
// EPI: 0 = fp32 store, 1 = bf16 hi/lo split store, 2 = tanh(x+bias) fp32
// ---------------------------------------------------------------------------
template <int EPI>
__global__ __launch_bounds__(256, 1)
void hmma_gemm(const __nv_bfloat16* __restrict__ Ah, const __nv_bfloat16* __restrict__ Al,
               const __nv_bfloat16* __restrict__ A2h, const __nv_bfloat16* __restrict__ A2l,
               int kSplit, int lda, int lda2, long aBatch,
               const __nv_bfloat16* __restrict__ Bh, const __nv_bfloat16* __restrict__ Bl,
               int ldb, long bBatch, int K,
               float* __restrict__ C, long cBatch, int ldc,
               __nv_bfloat16* __restrict__ Chi, __nv_bfloat16* __restrict__ Clo,
               const float* __restrict__ bias)
{
    extern __shared__ char smem[];
    const uint32_t sb = smem_u32(smem);
    const int tid = threadIdx.x;
    const int l   = tid & 31;
    const int wid = tid >> 5;
    const int wm  = wid >> 1;      // 0..3
    const int wn  = wid & 1;       // 0..1

    const int m0 = blockIdx.y * 128;
    const int n0 = blockIdx.x * 128;
    const int z  = blockIdx.z;
    Ah  += (long)z * aBatch;  Al  += (long)z * aBatch;
    A2h += (long)z * aBatch;  A2l += (long)z * aBatch;
    Bh  += (long)z * bBatch;  Bl  += (long)z * bBatch;

    const int nchunks = K / KC;

    // ---- cp.async loader for chunk c into stage s ----
    auto issue = [&](int c, int s) {
        if (c >= nchunks) return;
        const int k0 = c * KC;
        const __nv_bfloat16* pAh = Ah;
        const __nv_bfloat16* pAl = Al;
        int ak = k0, la = lda;
        if (k0 >= kSplit) { pAh = A2h; pAl = A2l; ak = k0 - kSplit; la = lda2; }
        const uint32_t st = sb + s * STG;
#pragma unroll
        for (int j = 0; j < 8; j++) {
            int idx  = tid + j * 256;
            int mat  = idx >> 9;          // 0..3
            int w    = idx & 511;
            int row  = w >> 2;            // 0..127
            int part = w & 3;             // 16B unit within 64B row
            uint32_t dst = st + mat * MATB + row * ROWB + part * 16;
            const __nv_bfloat16* src;
            if (mat == 0)      src = pAh + (long)(m0 + row) * la  + ak + part * 8;
            else if (mat == 1) src = pAl + (long)(m0 + row) * la  + ak + part * 8;
            else if (mat == 2) src = Bh  + (long)(n0 + row) * ldb + k0 + part * 8;
            else               src = Bl  + (long)(n0 + row) * ldb + k0 + part * 8;
            CP_ASYNC16(dst, src);
        }
    };

    float acc[2][8][4];
#pragma unroll
    for (int mf = 0; mf < 2; mf++)
#pragma unroll
        for (int nf = 0; nf < 8; nf++)
#pragma unroll
            for (int r = 0; r < 4; r++) acc[mf][nf][r] = 0.f;

    issue(0, 0); CP_COMMIT();
    issue(1, 1); CP_COMMIT();
    issue(2, 2); CP_COMMIT();

    // per-lane ldmatrix address components (constant across chunks)
    const int rowA  = l & 15;
    const int kselA = (l >> 4) << 3;          // 0 or 8 halves
    const int rowB  = wn * 64 + ((l >> 4) << 3) + (l & 7);
    const int kselB = ((l >> 3) & 1) << 3;    // 0 or 8 halves

    for (int c = 0; c < nchunks; c++) {
        CP_WAIT2();
        __syncthreads();
        const uint32_t base = sb + (c % NSTG) * STG;
#pragma unroll
        for (int ks = 0; ks < 2; ks++) {
            uint32_t a_hi[2][4], a_lo[2][4];
#pragma unroll
            for (int mf = 0; mf < 2; mf++) {
                uint32_t off = (uint32_t)(wm * 32 + mf * 16 + rowA) * ROWB +
                               (ks * 16 + kselA) * 2;
                LDM4(a_hi[mf], base + off);
                LDM4(a_lo[mf], base + MATB + off);
            }
            uint32_t b_hi[4][4], b_lo[4][4];
#pragma unroll
            for (int nf2 = 0; nf2 < 4; nf2++) {
                uint32_t off = (uint32_t)(rowB + nf2 * 16) * ROWB +
                               (ks * 16 + kselB) * 2;
                LDM4(b_hi[nf2], base + 2 * MATB + off);
                LDM4(b_lo[nf2], base + 3 * MATB + off);
            }
#pragma unroll
            for (int mf = 0; mf < 2; mf++)
#pragma unroll
                for (int nf2 = 0; nf2 < 4; nf2++)
#pragma unroll
                    for (int h = 0; h < 2; h++) {
                        const int nf = nf2 * 2 + h;
                        MMA_BF16(acc[mf][nf], a_hi[mf], b_hi[nf2][h * 2], b_hi[nf2][h * 2 + 1]);
                        MMA_BF16(acc[mf][nf], a_hi[mf], b_lo[nf2][h * 2], b_lo[nf2][h * 2 + 1]);
                        MMA_BF16(acc[mf][nf], a_lo[mf], b_hi[nf2][h * 2], b_hi[nf2][h * 2 + 1]);
                    }
        }
        __syncthreads();
        issue(c + 3, c % NSTG);
        CP_COMMIT();
    }

    // ---- epilogue ----
    float* Cb = C + (long)z * cBatch;
    __nv_bfloat16* Chb = Chi + (long)z * cBatch;
    __nv_bfloat16* Clb = Clo + (long)z * cBatch;
#pragma unroll
    for (int mf = 0; mf < 2; mf++)
#pragma unroll
        for (int nf = 0; nf < 8; nf++)
#pragma unroll
            for (int h2 = 0; h2 < 2; h2++) {
                const int m = m0 + wm * 32 + mf * 16 + h2 * 8 + (l >> 2);
                const int n = n0 + wn * 64 + nf * 8 + (l & 3) * 2;
                float v0 = acc[mf][nf][h2 * 2 + 0];
                float v1 = acc[mf][nf][h2 * 2 + 1];
                if (EPI == 0) {
                    float2 t = make_float2(v0, v1);
                    *(float2*)&Cb[(long)m * ldc + n] = t;
                } else if (EPI == 2) {
                    float2 t;
                    t.x = tanhf(v0 + bias[n]);
                    t.y = tanhf(v1 + bias[n + 1]);
                    *(float2*)&Cb[(long)m * ldc + n] = t;
                } else {
                    __nv_bfloat16 h0 = __float2bfloat16(v0);
                    __nv_bfloat16 h1 = __float2bfloat16(v1);
                    __nv_bfloat16 l0 = __float2bfloat16(v0 - __bfloat162float(h0));
                    __nv_bfloat16 l1 = __float2bfloat16(v1 - __bfloat162float(h1));
                    __nv_bfloat162 hp; hp.x = h0; hp.y = h1;
                    __nv_bfloat162 lp; lp.x = l0; lp.y = l1;
                    *(__nv_bfloat162*)&Chb[(long)m * ldc + n] = hp;
                    *(__nv_bfloat162*)&Clb[(long)m * ldc + n] = lp;
                }
            }
}

// ---------------------------------------------------------------------------
// fp32 -> bf16 hi/lo split (elementwise)
// ---------------------------------------------------------------------------
__global__ __launch_bounds__(256)
void cvt_hilo(const float* __restrict__ x, __nv_bfloat16* __restrict__ hi,
              __nv_bfloat16* __restrict__ lo, long n4)
{
    long i = (long)blockIdx.x * blockDim.x + threadIdx.x;
    if (i >= n4) return;
    float4 v = ((const float4*)x)[i];
    float f[4] = {v.x, v.y, v.z, v.w};
    __nv_bfloat16 h[4], l[4];
#pragma unroll
    for (int j = 0; j < 4; j++) {
        h[j] = __float2bfloat16(f[j]);
        l[j] = __float2bfloat16(f[j] - __bfloat162float(h[j]));
    }
    *(uint2*)&hi[i * 4] = *(uint2*)h;
    *(uint2*)&lo[i * 4] = *(uint2*)l;
}

// ---------------------------------------------------------------------------
// ctx [B,S,H] fp32 -> ctxT hi/lo [B,H,S] bf16 (tiled transpose + split)
// ---------------------------------------------------------------------------
__global__ __launch_bounds__(256)
void transpose_cvt(const float* __restrict__ ctx, __nv_bfloat16* __restrict__ thi,
                   __nv_bfloat16* __restrict__ tlo)
{
    __shared__ float tile[32][33];
    const int h0 = blockIdx.x * 32;
    const int s0 = blockIdx.y * 32;
    const int z  = blockIdx.z;
    const int tx = threadIdx.x & 31;
    const int ty = threadIdx.x >> 5;   // 0..7
    const long ibase = (long)z * Ss * Hh;
    const long obase = (long)z * Hh * Ss;
#pragma unroll
    for (int i = 0; i < 4; i++) {
        int s = s0 + ty + i * 8;
        tile[ty + i * 8][tx] = ctx[ibase + (long)s * Hh + h0 + tx];
    }
    __syncthreads();
#pragma unroll
    for (int i = 0; i < 4; i++) {
        int h = h0 + ty + i * 8;
        float v = tile[tx][ty + i * 8];
        __nv_bfloat16 hb = __float2bfloat16(v);
        __nv_bfloat16 lb = __float2bfloat16(v - __bfloat162float(hb));
        long o = obase + (long)h * Ss + s0 + tx;
        thi[o] = hb;
        tlo[o] = lb;
    }
}

// ---------------------------------------------------------------------------
// In-place row softmax over S=2048, also emits bf16 hi/lo of result.
// ---------------------------------------------------------------------------
__global__ __launch_bounds__(256)
void softmax_kernel(float* __restrict__ attn, __nv_bfloat16* __restrict__ ahi,
                    __nv_bfloat16* __restrict__ alo)
{
    __shared__ float red[256];
    const long row = blockIdx.x;
    float* p = attn + row * (long)Ss;
    const int tid = threadIdx.x;

    float v[8];
    float mx = -INFINITY;
#pragma unroll
    for (int i = 0; i < 8; i++) {
        v[i] = p[tid + i * 256];
        mx = fmaxf(mx, v[i]);
    }
    red[tid] = mx;
    __syncthreads();
    for (int s = 128; s > 0; s >>= 1) {
        if (tid < s) red[tid] = fmaxf(red[tid], red[tid + s]);
        __syncthreads();
    }
    mx = red[0];
    __syncthreads();

    float sum = 0.f;
#pragma unroll
    for (int i = 0; i < 8; i++) {
        v[i] = __expf(v[i] - mx);
        sum += v[i];
    }
    red[tid] = sum;
    __syncthreads();
    for (int s = 128; s > 0; s >>= 1) {
        if (tid < s) red[tid] += red[tid + s];
        __syncthreads();
    }
    const float inv = 1.f / red[0];
#pragma unroll
    for (int i = 0; i < 8; i++) {
        float w = v[i] * inv;
        long idx = row * (long)Ss + tid + i * 256;
        p[tid + i * 256] = w;
        __nv_bfloat16 hb = __float2bfloat16(w);
        ahi[idx] = hb;
        alo[idx] = __float2bfloat16(w - __bfloat162float(hb));
    }
}

// ---------------------------------------------------------------------------
extern "C" void kernel_launch(void* const* d_in, const int* in_sizes, int n_in,
                              void* d_out, int out_size)
{
    const float* output  = (const float*)d_in[0];  // [B,T,H]
    const float* context = (const float*)d_in[1];  // [B,S,H]
    const float* attn_w  = (const float*)d_in[2];  // [H,H]
    const float* w2      = (const float*)d_in[3];  // [H,2H]
    const float* b2      = (const float*)d_in[4];  // [H]

    float* out  = (float*)d_out;                   // [B,T,H]
    float* attn = out + (long)MT * Hh;             // [B,T,S]

    void *outhi, *outlo, *whi, *wlo, *w2hi, *w2lo, *ctxhi, *ctxlo;
    void *ctxthi, *ctxtlo, *qhi, *qlo, *athi, *atlo, *mixhi, *mixlo;
    cudaGetSymbolAddress(&outhi, g_out_hi);   cudaGetSymbolAddress(&outlo, g_out_lo);
    cudaGetSymbolAddress(&whi, g_w_hi);       cudaGetSymbolAddress(&wlo, g_w_lo);
    cudaGetSymbolAddress(&w2hi, g_w2_hi);     cudaGetSymbolAddress(&w2lo, g_w2_lo);
    cudaGetSymbolAddress(&ctxhi, g_ctx_hi);   cudaGetSymbolAddress(&ctxlo, g_ctx_lo);
    cudaGetSymbolAddress(&ctxthi, g_ctxT_hi); cudaGetSymbolAddress(&ctxtlo, g_ctxT_lo);
    cudaGetSymbolAddress(&qhi, g_q_hi);       cudaGetSymbolAddress(&qlo, g_q_lo);
    cudaGetSymbolAddress(&athi, g_attn_hi);   cudaGetSymbolAddress(&atlo, g_attn_lo);
    cudaGetSymbolAddress(&mixhi, g_mix_hi);   cudaGetSymbolAddress(&mixlo, g_mix_lo);

    cudaFuncSetAttribute(hmma_gemm<0>, cudaFuncAttributeMaxDynamicSharedMemorySize, SMEM_TOTAL);
    cudaFuncSetAttribute(hmma_gemm<1>, cudaFuncAttributeMaxDynamicSharedMemorySize, SMEM_TOTAL);
    cudaFuncSetAttribute(hmma_gemm<2>, cudaFuncAttributeMaxDynamicSharedMemorySize, SMEM_TOTAL);

    const __nv_bfloat16* OH = (const __nv_bfloat16*)outhi;
    const __nv_bfloat16* OL = (const __nv_bfloat16*)outlo;
    const __nv_bfloat16* WH = (const __nv_bfloat16*)whi;
    const __nv_bfloat16* WL = (const __nv_bfloat16*)wlo;
    const __nv_bfloat16* W2H = (const __nv_bfloat16*)w2hi;
    const __nv_bfloat16* W2L = (const __nv_bfloat16*)w2lo;
    const __nv_bfloat16* CH = (const __nv_bfloat16*)ctxhi;
    const __nv_bfloat16* CL = (const __nv_bfloat16*)ctxlo;
    const __nv_bfloat16* CTH = (const __nv_bfloat16*)ctxthi;
    const __nv_bfloat16* CTL = (const __nv_bfloat16*)ctxtlo;
    const __nv_bfloat16* QH = (const __nv_bfloat16*)qhi;
    const __nv_bfloat16* QL = (const __nv_bfloat16*)qlo;
    const __nv_bfloat16* AH = (const __nv_bfloat16*)athi;
    const __nv_bfloat16* AL = (const __nv_bfloat16*)atlo;
    const __nv_bfloat16* MH = (const __nv_bfloat16*)mixhi;
    const __nv_bfloat16* ML = (const __nv_bfloat16*)mixlo;

    // ---- 1) preconvert inputs ----
    cvt_hilo<<<(MT * (long)Hh / 4 + 255) / 256, 256>>>(output, (__nv_bfloat16*)outhi, (__nv_bfloat16*)outlo, MT * (long)Hh / 4);
    cvt_hilo<<<((long)Hh * Hh / 4 + 255) / 256, 256>>>(attn_w, (__nv_bfloat16*)whi, (__nv_bfloat16*)wlo, (long)Hh * Hh / 4);
    cvt_hilo<<<((long)Hh * 2 * Hh / 4 + 255) / 256, 256>>>(w2, (__nv_bfloat16*)w2hi, (__nv_bfloat16*)w2lo, (long)Hh * 2 * Hh / 4);
    cvt_hilo<<<((long)Bb * Ss * Hh / 4 + 255) / 256, 256>>>(context, (__nv_bfloat16*)ctxhi, (__nv_bfloat16*)ctxlo, (long)Bb * Ss * Hh / 4);
    {
        dim3 g(Hh / 32, Ss / 32, Bb);
        transpose_cvt<<<g, 256>>>(context, (__nv_bfloat16*)ctxthi, (__nv_bfloat16*)ctxtlo);
    }

    // ---- 2) q = output @ W^T  -> q hi/lo  (M=MT, N=H, K=H) ----
    {
        dim3 grid(Hh / 128, MT / 128, 1);
        hmma_gemm<1><<<grid, 256, SMEM_TOTAL>>>(OH, OL, OH, OL, 1 << 30, Hh, Hh, 0L,
                                                WH, WL, Hh, 0L, Hh,
                                                nullptr, (long)MT * Hh, Hh,
                                                (__nv_bfloat16*)qhi, (__nv_bfloat16*)qlo, nullptr);
    }
    // ---- 3) scores = q @ ctx^T (batched) -> attn fp32 (M=T, N=S, K=H) ----
    {
        dim3 grid(Ss / 128, Tt / 128, Bb);
        hmma_gemm<0><<<grid, 256, SMEM_TOTAL>>>(QH, QL, QH, QL, 1 << 30, Hh, Hh, (long)Tt * Hh,
                                                CH, CL, Hh, (long)Ss * Hh, Hh,
                                                attn, (long)Tt * Ss, Ss,
                                                (__nv_bfloat16*)athi, (__nv_bfloat16*)atlo, nullptr);
    }
    // ---- 4) softmax in place + hi/lo emit ----
    softmax_kernel<<<MT, 256>>>(attn, (__nv_bfloat16*)athi, (__nv_bfloat16*)atlo);

    // ---- 5) mix = attn @ ctx (batched, via ctxT) -> mix hi/lo (M=T, N=H, K=S) ----
    {
        dim3 grid(Hh / 128, Tt / 128, Bb);
        hmma_gemm<1><<<grid, 256, SMEM_TOTAL>>>(AH, AL, AH, AL, 1 << 30, Ss, Ss, (long)Tt * Ss,
                                                CTH, CTL, Ss, (long)Hh * Ss, Ss,
                                                nullptr, (long)Tt * Hh, Hh,
                                                (__nv_bfloat16*)mixhi, (__nv_bfloat16*)mixlo, nullptr);
    }
    // ---- 6) out = tanh([mix|q] @ W2^T + b2)  (M=MT, N=H, K=2H) ----
    {
        dim3 grid(Hh / 128, MT / 128, 1);
        hmma_gemm<2><<<grid, 256, SMEM_TOTAL>>>(MH, ML, QH, QL, Hh, Hh, Hh, 0L,
                                                W2H, W2L, 2 * Hh, 0L, 2 * Hh,
                                                out, (long)MT * Hh, Hh,
                                                nullptr, nullptr, b2);
    }
}

// round 9
// speedup vs baseline: 2.3184x; 1.0529x over previous
#include <cuda_runtime.h>
#include <cuda_bf16.h>
#include <math.h>
#include <stdint.h>

#define Bb 16
#define Tt 1024
#define Ss 2048
#define Hh 1024
#define MT 16384          // B*T

// ---------------- global scratch (allocation-free rule) ---------------------
__device__ __nv_bfloat16 g_out_hi[(long)MT * Hh],  g_out_lo[(long)MT * Hh];
__device__ __nv_bfloat16 g_w_hi[(long)Hh * Hh],    g_w_lo[(long)Hh * Hh];
__device__ __nv_bfloat16 g_w2_hi[(long)Hh * 2 * Hh], g_w2_lo[(long)Hh * 2 * Hh];
__device__ __nv_bfloat16 g_ctx_hi[(long)Bb * Ss * Hh], g_ctx_lo[(long)Bb * Ss * Hh];
__device__ __nv_bfloat16 g_ctxT_hi[(long)Bb * Hh * Ss], g_ctxT_lo[(long)Bb * Hh * Ss];
__device__ __nv_bfloat16 g_q_hi[(long)MT * Hh],    g_q_lo[(long)MT * Hh];
__device__ __nv_bfloat16 g_attn_hi[(long)MT * Ss], g_attn_lo[(long)MT * Ss];
__device__ __nv_bfloat16 g_mix_hi[(long)MT * Hh],  g_mix_lo[(long)MT * Hh];

// ---------------- PTX helpers (all sm_80+ arch-agnostic) --------------------
__device__ __forceinline__ uint32_t smem_u32(const void* p) {
    uint32_t a;
    asm("{ .reg .u64 t; cvta.to.shared.u64 t, %1; cvt.u32.u64 %0, t; }" : "=r"(a) : "l"(p));
    return a;
}
#define CP_ASYNC16(dst, src) \
    asm volatile("cp.async.cg.shared.global [%0], [%1], 16;" :: "r"(dst), "l"(src) : "memory")
#define CP_COMMIT() asm volatile("cp.async.commit_group;" ::: "memory")
#define CP_WAIT2()  asm volatile("cp.async.wait_group 2;" ::: "memory")

#define LDM4(r, a) \
    asm volatile("ldmatrix.sync.aligned.m8n8.x4.shared.b16 {%0,%1,%2,%3}, [%4];" \
        : "=r"((r)[0]), "=r"((r)[1]), "=r"((r)[2]), "=r"((r)[3]) : "r"(a))

#define MMA_BF16(d, a, b0, b1) \
    asm volatile("mma.sync.aligned.m16n8k16.row.col.f32.bf16.bf16.f32 " \
        "{%0,%1,%2,%3}, {%4,%5,%6,%7}, {%8,%9}, {%0,%1,%2,%3};" \
        : "+f"((d)[0]), "+f"((d)[1]), "+f"((d)[2]), "+f"((d)[3]) \
        : "r"((a)[0]), "r"((a)[1]), "r"((a)[2]), "r"((a)[3]), "r"(b0), "r"(b1))

// Tile sizes: CTA 128(M) x 256(N), 8 warps (2m x 4n), warp tile 64x64, KC=32.
#define ROWB   80          // bytes per smem row (40 halves: 32 data + 8 pad)
#define AMATB  10240       // A matrix bytes per stage (128 rows)
#define BMATB  20480       // B matrix bytes per stage (256 rows)
#define STG    61440       // 2*AMATB + 2*BMATB
#define NSTG   3
#define SMEM_TOTAL (NSTG * STG)   // 184320
#define KC     32

// ---------------------------------------------------------------------------
// HMMA bf16 GEMM with 2-term hi/lo split: C[M,N] = A[M,K] * B[N,K]^T
// EPI: 0 = fp32 store, 1 = bf16 hi/lo split store, 2 = tanh(x+bias) fp32
// ---------------------------------------------------------------------------
template <int EPI>
__global__ __launch_bounds__(256, 1)
void hmma_gemm(const __nv_bfloat16* __restrict__ Ah, const __nv_bfloat16* __restrict__ Al,
               const __nv_bfloat16* __restrict__ A2h, const __nv_bfloat16* __restrict__ A2l,
               int kSplit, int lda, int lda2, long aBatch,
               const __nv_bfloat16* __restrict__ Bh, const __nv_bfloat16* __restrict__ Bl,
               int ldb, long bBatch, int K,
               float* __restrict__ C, long cBatch, int ldc,
               __nv_bfloat16* __restrict__ Chi, __nv_bfloat16* __restrict__ Clo,
               const float* __restrict__ bias)
{
    extern __shared__ char smem[];
    const uint32_t sb = smem_u32(smem);
    const int tid = threadIdx.x;
    const int l   = tid & 31;
    const int wid = tid >> 5;
    const int wm  = wid >> 2;      // 0..1  (64 M-rows each)
    const int wn  = wid & 3;       // 0..3  (64 N-cols each)

    const int m0 = blockIdx.y * 128;
    const int n0 = blockIdx.x * 256;
    const int z  = blockIdx.z;
    Ah  += (long)z * aBatch;  Al  += (long)z * aBatch;
    A2h += (long)z * aBatch;  A2l += (long)z * aBatch;
    Bh  += (long)z * bBatch;  Bl  += (long)z * bBatch;

    const int nchunks = K / KC;

    // ---- cp.async loader for chunk c into stage s ----
    auto issue = [&](int c, int s) {
        if (c >= nchunks) return;
        const int k0 = c * KC;
        const __nv_bfloat16* pAh = Ah;
        const __nv_bfloat16* pAl = Al;
        int ak = k0, la = lda;
        if (k0 >= kSplit) { pAh = A2h; pAl = A2l; ak = k0 - kSplit; la = lda2; }
        const uint32_t st = sb + s * STG;
#pragma unroll
        for (int j = 0; j < 12; j++) {
            int idx = tid + j * 256;          // 0..3071
            uint32_t dst;
            const __nv_bfloat16* src;
            if (idx < 1024) {                  // A hi/lo: 128 rows x 4 parts
                int mat = idx >> 9;            // 0=hi 1=lo
                int i2  = idx & 511;
                int row = i2 >> 2;
                int part = i2 & 3;
                dst = st + mat * AMATB + (uint32_t)row * ROWB + part * 16;
                const __nv_bfloat16* p = mat ? pAl : pAh;
                src = p + (long)(m0 + row) * la + ak + part * 8;
            } else {                           // B hi/lo: 256 rows x 4 parts
                int i3  = idx - 1024;          // 0..2047
                int mat = i3 >> 10;            // 0=hi 1=lo
                int i2  = i3 & 1023;
                int row = i2 >> 2;
                int part = i2 & 3;
                dst = st + 2 * AMATB + mat * BMATB + (uint32_t)row * ROWB + part * 16;
                const __nv_bfloat16* p = mat ? Bl : Bh;
                src = p + (long)(n0 + row) * ldb + k0 + part * 8;
            }
            CP_ASYNC16(dst, src);
        }
    };

    float acc[4][8][4];
#pragma unroll
    for (int mf = 0; mf < 4; mf++)
#pragma unroll
        for (int nf = 0; nf < 8; nf++)
#pragma unroll
            for (int r = 0; r < 4; r++) acc[mf][nf][r] = 0.f;

    issue(0, 0); CP_COMMIT();
    issue(1, 1); CP_COMMIT();
    issue(2, 2); CP_COMMIT();

    // per-lane ldmatrix address components (constant across chunks)
    const int rowA  = l & 15;
    const int kselA = (l >> 4) << 3;          // 0 or 8 halves
    const int rowB  = wn * 64 + ((l >> 4) << 3) + (l & 7);
    const int kselB = ((l >> 3) & 1) << 3;    // 0 or 8 halves

    for (int c = 0; c < nchunks; c++) {
        CP_WAIT2();
        __syncthreads();
        const uint32_t base = sb + (c % NSTG) * STG;
#pragma unroll
        for (int ks = 0; ks < 2; ks++) {
            uint32_t a_hi[4][4], a_lo[4][4];
#pragma unroll
            for (int mf = 0; mf < 4; mf++) {
                uint32_t off = (uint32_t)(wm * 64 + mf * 16 + rowA) * ROWB +
                               (ks * 16 + kselA) * 2;
                LDM4(a_hi[mf], base + off);
                LDM4(a_lo[mf], base + AMATB + off);
            }
            uint32_t b_hi[4][4], b_lo[4][4];
#pragma unroll
            for (int nf2 = 0; nf2 < 4; nf2++) {
                uint32_t off = (uint32_t)(rowB + nf2 * 16) * ROWB +
                               (ks * 16 + kselB) * 2;
                LDM4(b_hi[nf2], base + 2 * AMATB + off);
                LDM4(b_lo[nf2], base + 2 * AMATB + BMATB + off);
            }
#pragma unroll
            for (int mf = 0; mf < 4; mf++)
#pragma unroll
                for (int nf2 = 0; nf2 < 4; nf2++)
#pragma unroll
                    for (int h = 0; h < 2; h++) {
                        const int nf = nf2 * 2 + h;
                        MMA_BF16(acc[mf][nf], a_hi[mf], b_hi[nf2][h * 2], b_hi[nf2][h * 2 + 1]);
                        MMA_BF16(acc[mf][nf], a_hi[mf], b_lo[nf2][h * 2], b_lo[nf2][h * 2 + 1]);
                        MMA_BF16(acc[mf][nf], a_lo[mf], b_hi[nf2][h * 2], b_hi[nf2][h * 2 + 1]);
                    }
        }
        __syncthreads();
        issue(c + 3, c % NSTG);
        CP_COMMIT();
    }

    // ---- epilogue ----
    float* Cb = C + (long)z * cBatch;
    __nv_bfloat16* Chb = Chi + (long)z * cBatch;
    __nv_bfloat16* Clb = Clo + (long)z * cBatch;
#pragma unroll
    for (int mf = 0; mf < 4; mf++)
#pragma unroll
        for (int nf = 0; nf < 8; nf++)
#pragma unroll
            for (int h2 = 0; h2 < 2; h2++) {
                const int m = m0 + wm * 64 + mf * 16 + h2 * 8 + (l >> 2);
                const int n = n0 + wn * 64 + nf * 8 + (l & 3) * 2;
                float v0 = acc[mf][nf][h2 * 2 + 0];
                float v1 = acc[mf][nf][h2 * 2 + 1];
                if (EPI == 0) {
                    float2 t = make_float2(v0, v1);
                    *(float2*)&Cb[(long)m * ldc + n] = t;
                } else if (EPI == 2) {
                    float2 t;
                    t.x = tanhf(v0 + bias[n]);
                    t.y = tanhf(v1 + bias[n + 1]);
                    *(float2*)&Cb[(long)m * ldc + n] = t;
                } else {
                    __nv_bfloat16 h0 = __float2bfloat16(v0);
                    __nv_bfloat16 h1 = __float2bfloat16(v1);
                    __nv_bfloat16 l0 = __float2bfloat16(v0 - __bfloat162float(h0));
                    __nv_bfloat16 l1 = __float2bfloat16(v1 - __bfloat162float(h1));
                    __nv_bfloat162 hp; hp.x = h0; hp.y = h1;
                    __nv_bfloat162 lp; lp.x = l0; lp.y = l1;
                    *(__nv_bfloat162*)&Chb[(long)m * ldc + n] = hp;
                    *(__nv_bfloat162*)&Clb[(long)m * ldc + n] = lp;
                }
            }
}

// ---------------------------------------------------------------------------
// fp32 -> bf16 hi/lo split (elementwise)
// ---------------------------------------------------------------------------
__global__ __launch_bounds__(256)
void cvt_hilo(const float* __restrict__ x, __nv_bfloat16* __restrict__ hi,
              __nv_bfloat16* __restrict__ lo, long n4)
{
    long i = (long)blockIdx.x * blockDim.x + threadIdx.x;
    if (i >= n4) return;
    float4 v = ((const float4*)x)[i];
    float f[4] = {v.x, v.y, v.z, v.w};
    __nv_bfloat16 h[4], l[4];
#pragma unroll
    for (int j = 0; j < 4; j++) {
        h[j] = __float2bfloat16(f[j]);
        l[j] = __float2bfloat16(f[j] - __bfloat162float(h[j]));
    }
    *(uint2*)&hi[i * 4] = *(uint2*)h;
    *(uint2*)&lo[i * 4] = *(uint2*)l;
}

// ---------------------------------------------------------------------------
// ctx [B,S,H] fp32 -> ctx hi/lo [B,S,H] + ctxT hi/lo [B,H,S]  (one read)
// ---------------------------------------------------------------------------
__global__ __launch_bounds__(256)
void transpose_cvt(const float* __restrict__ ctx,
                   __nv_bfloat16* __restrict__ chi, __nv_bfloat16* __restrict__ clo,
                   __nv_bfloat16* __restrict__ thi, __nv_bfloat16* __restrict__ tlo)
{
    __shared__ float tile[32][33];
    const int h0 = blockIdx.x * 32;
    const int s0 = blockIdx.y * 32;
    const int z  = blockIdx.z;
    const int tx = threadIdx.x & 31;
    const int ty = threadIdx.x >> 5;   // 0..7
    const long ibase = (long)z * Ss * Hh;
    const long obase = (long)z * Hh * Ss;
#pragma unroll
    for (int i = 0; i < 4; i++) {
        int s = s0 + ty + i * 8;
        float v = ctx[ibase + (long)s * Hh + h0 + tx];
        tile[ty + i * 8][tx] = v;
        __nv_bfloat16 hb = __float2bfloat16(v);
        __nv_bfloat16 lb = __float2bfloat16(v - __bfloat162float(hb));
        long o = ibase + (long)s * Hh + h0 + tx;
        chi[o] = hb;
        clo[o] = lb;
    }
    __syncthreads();
#pragma unroll
    for (int i = 0; i < 4; i++) {
        int h = h0 + ty + i * 8;
        float v = tile[tx][ty + i * 8];
        __nv_bfloat16 hb = __float2bfloat16(v);
        __nv_bfloat16 lb = __float2bfloat16(v - __bfloat162float(hb));
        long o = obase + (long)h * Ss + s0 + tx;
        thi[o] = hb;
        tlo[o] = lb;
    }
}

// ---------------------------------------------------------------------------
// In-place row softmax over S=2048, also emits bf16 hi/lo of result.
// ---------------------------------------------------------------------------
__global__ __launch_bounds__(256)
void softmax_kernel(float* __restrict__ attn, __nv_bfloat16* __restrict__ ahi,
                    __nv_bfloat16* __restrict__ alo)
{
    __shared__ float red[256];
    const long row = blockIdx.x;
    float* p = attn + row * (long)Ss;
    const int tid = threadIdx.x;

    float v[8];
    float mx = -INFINITY;
#pragma unroll
    for (int i = 0; i < 8; i++) {
        v[i] = p[tid + i * 256];
        mx = fmaxf(mx, v[i]);
    }
    red[tid] = mx;
    __syncthreads();
    for (int s = 128; s > 0; s >>= 1) {
        if (tid < s) red[tid] = fmaxf(red[tid], red[tid + s]);
        __syncthreads();
    }
    mx = red[0];
    __syncthreads();

    float sum = 0.f;
#pragma unroll
    for (int i = 0; i < 8; i++) {
        v[i] = __expf(v[i] - mx);
        sum += v[i];
    }
    red[tid] = sum;
    __syncthreads();
    for (int s = 128; s > 0; s >>= 1) {
        if (tid < s) red[tid] += red[tid + s];
        __syncthreads();
    }
    const float inv = 1.f / red[0];
#pragma unroll
    for (int i = 0; i < 8; i++) {
        float w = v[i] * inv;
        long idx = row * (long)Ss + tid + i * 256;
        p[tid + i * 256] = w;
        __nv_bfloat16 hb = __float2bfloat16(w);
        ahi[idx] = hb;
        alo[idx] = __float2bfloat16(w - __bfloat162float(hb));
    }
}

// ---------------------------------------------------------------------------
extern "C" void kernel_launch(void* const* d_in, const int* in_sizes, int n_in,
                              void* d_out, int out_size)
{
    const float* output  = (const float*)d_in[0];  // [B,T,H]
    const float* context = (const float*)d_in[1];  // [B,S,H]
    const float* attn_w  = (const float*)d_in[2];  // [H,H]
    const float* w2      = (const float*)d_in[3];  // [H,2H]
    const float* b2      = (const float*)d_in[4];  // [H]

    float* out  = (float*)d_out;                   // [B,T,H]
    float* attn = out + (long)MT * Hh;             // [B,T,S]

    void *outhi, *outlo, *whi, *wlo, *w2hi, *w2lo, *ctxhi, *ctxlo;
    void *ctxthi, *ctxtlo, *qhi, *qlo, *athi, *atlo, *mixhi, *mixlo;
    cudaGetSymbolAddress(&outhi, g_out_hi);   cudaGetSymbolAddress(&outlo, g_out_lo);
    cudaGetSymbolAddress(&whi, g_w_hi);       cudaGetSymbolAddress(&wlo, g_w_lo);
    cudaGetSymbolAddress(&w2hi, g_w2_hi);     cudaGetSymbolAddress(&w2lo, g_w2_lo);
    cudaGetSymbolAddress(&ctxhi, g_ctx_hi);   cudaGetSymbolAddress(&ctxlo, g_ctx_lo);
    cudaGetSymbolAddress(&ctxthi, g_ctxT_hi); cudaGetSymbolAddress(&ctxtlo, g_ctxT_lo);
    cudaGetSymbolAddress(&qhi, g_q_hi);       cudaGetSymbolAddress(&qlo, g_q_lo);
    cudaGetSymbolAddress(&athi, g_attn_hi);   cudaGetSymbolAddress(&atlo, g_attn_lo);
    cudaGetSymbolAddress(&mixhi, g_mix_hi);   cudaGetSymbolAddress(&mixlo, g_mix_lo);

    cudaFuncSetAttribute(hmma_gemm<0>, cudaFuncAttributeMaxDynamicSharedMemorySize, SMEM_TOTAL);
    cudaFuncSetAttribute(hmma_gemm<1>, cudaFuncAttributeMaxDynamicSharedMemorySize, SMEM_TOTAL);
    cudaFuncSetAttribute(hmma_gemm<2>, cudaFuncAttributeMaxDynamicSharedMemorySize, SMEM_TOTAL);

    const __nv_bfloat16* OH = (const __nv_bfloat16*)outhi;
    const __nv_bfloat16* OL = (const __nv_bfloat16*)outlo;
    const __nv_bfloat16* WH = (const __nv_bfloat16*)whi;
    const __nv_bfloat16* WL = (const __nv_bfloat16*)wlo;
    const __nv_bfloat16* W2H = (const __nv_bfloat16*)w2hi;
    const __nv_bfloat16* W2L = (const __nv_bfloat16*)w2lo;
    const __nv_bfloat16* CH = (const __nv_bfloat16*)ctxhi;
    const __nv_bfloat16* CL = (const __nv_bfloat16*)ctxlo;
    const __nv_bfloat16* CTH = (const __nv_bfloat16*)ctxthi;
    const __nv_bfloat16* CTL = (const __nv_bfloat16*)ctxtlo;
    const __nv_bfloat16* QH = (const __nv_bfloat16*)qhi;
    const __nv_bfloat16* QL = (const __nv_bfloat16*)qlo;
    const __nv_bfloat16* AH = (const __nv_bfloat16*)athi;
    const __nv_bfloat16* AL = (const __nv_bfloat16*)atlo;
    const __nv_bfloat16* MH = (const __nv_bfloat16*)mixhi;
    const __nv_bfloat16* ML = (const __nv_bfloat16*)mixlo;

    // ---- 1) preconvert inputs ----
    cvt_hilo<<<(MT * (long)Hh / 4 + 255) / 256, 256>>>(output, (__nv_bfloat16*)outhi, (__nv_bfloat16*)outlo, MT * (long)Hh / 4);
    cvt_hilo<<<((long)Hh * Hh / 4 + 255) / 256, 256>>>(attn_w, (__nv_bfloat16*)whi, (__nv_bfloat16*)wlo, (long)Hh * Hh / 4);
    cvt_hilo<<<((long)Hh * 2 * Hh / 4 + 255) / 256, 256>>>(w2, (__nv_bfloat16*)w2hi, (__nv_bfloat16*)w2lo, (long)Hh * 2 * Hh / 4);
    {
        dim3 g(Hh / 32, Ss / 32, Bb);
        transpose_cvt<<<g, 256>>>(context, (__nv_bfloat16*)ctxhi, (__nv_bfloat16*)ctxlo,
                                  (__nv_bfloat16*)ctxthi, (__nv_bfloat16*)ctxtlo);
    }

    // ---- 2) q = output @ W^T  -> q hi/lo  (M=MT, N=H, K=H) ----
    {
        dim3 grid(Hh / 256, MT / 128, 1);
        hmma_gemm<1><<<grid, 256, SMEM_TOTAL>>>(OH, OL, OH, OL, 1 << 30, Hh, Hh, 0L,
                                                WH, WL, Hh, 0L, Hh,
                                                nullptr, (long)MT * Hh, Hh,
                                                (__nv_bfloat16*)qhi, (__nv_bfloat16*)qlo, nullptr);
    }
    // ---- 3) scores = q @ ctx^T (batched) -> attn fp32 (M=T, N=S, K=H) ----
    {
        dim3 grid(Ss / 256, Tt / 128, Bb);
        hmma_gemm<0><<<grid, 256, SMEM_TOTAL>>>(QH, QL, QH, QL, 1 << 30, Hh, Hh, (long)Tt * Hh,
                                                CH, CL, Hh, (long)Ss * Hh, Hh,
                                                attn, (long)Tt * Ss, Ss,
                                                (__nv_bfloat16*)athi, (__nv_bfloat16*)atlo, nullptr);
    }
    // ---- 4) softmax in place + hi/lo emit ----
    softmax_kernel<<<MT, 256>>>(attn, (__nv_bfloat16*)athi, (__nv_bfloat16*)atlo);

    // ---- 5) mix = attn @ ctx (batched, via ctxT) -> mix hi/lo (M=T, N=H, K=S) ----
    {
        dim3 grid(Hh / 256, Tt / 128, Bb);
        hmma_gemm<1><<<grid, 256, SMEM_TOTAL>>>(AH, AL, AH, AL, 1 << 30, Ss, Ss, (long)Tt * Ss,
                                                CTH, CTL, Ss, (long)Hh * Ss, Ss,
                                                nullptr, (long)Tt * Hh, Hh,
                                                (__nv_bfloat16*)mixhi, (__nv_bfloat16*)mixlo, nullptr);
    }
    // ---- 6) out = tanh([mix|q] @ W2^T + b2)  (M=MT, N=H, K=2H) ----
    {
        dim3 grid(Hh / 256, MT / 128, 1);
        hmma_gemm<2><<<grid, 256, SMEM_TOTAL>>>(MH, ML, QH, QL, Hh, Hh, Hh, 0L,
                                                W2H, W2L, 2 * Hh, 0L, 2 * Hh,
                                                out, (long)MT * Hh, Hh,
                                                nullptr, nullptr, b2);
    }
}